// round 6
// baseline (speedup 1.0000x reference)
#include <cuda_runtime.h>
#include <stdint.h>

#define NB 32
#define NC 4
#define NS 256
#define NL 256
#define NDIN 256
#define NDOUT 256

// Scratch (static device globals: allocation-free per harness rules)
__device__ float g_adj[NB * NS * NS];                 // 8 MB, entries exactly {0,1}
__device__ float g_invdeg[NB * NS];                   // 32 KB
__device__ float g_Y[(size_t)NB * NC * NS * NDIN];    // 33.5 MB

// ---------------------------------------------------------------------------
// Threefry-2x32 with key = (0, 42)  (jax.random.key(42))
// ---------------------------------------------------------------------------
__device__ __forceinline__ void threefry(uint32_t x0, uint32_t x1,
                                         uint32_t& o0, uint32_t& o1) {
  const uint32_t ks0 = 0u;
  const uint32_t ks1 = 42u;
  const uint32_t ks2 = 0u ^ 42u ^ 0x1BD11BDAu;
  x0 += ks0; x1 += ks1;
#define TF_R(r) { x0 += x1; x1 = __funnelshift_l(x1, x1, (r)); x1 ^= x0; }
  TF_R(13) TF_R(15) TF_R(26) TF_R(6)
  x0 += ks1; x1 += ks2 + 1u;
  TF_R(17) TF_R(29) TF_R(16) TF_R(24)
  x0 += ks2; x1 += ks0 + 2u;
  TF_R(13) TF_R(15) TF_R(26) TF_R(6)
  x0 += ks0; x1 += ks1 + 3u;
  TF_R(17) TF_R(29) TF_R(16) TF_R(24)
  x0 += ks1; x1 += ks2 + 4u;
  TF_R(13) TF_R(15) TF_R(26) TF_R(6)
  x0 += ks2; x1 += ks0 + 5u;
#undef TF_R
  o0 = x0; o1 = x1;
}

// Partitionable threefry (JAX >= 0.4.36 default), 32-bit draws:
//   counts = iota(uint64); (b1, b2) = threefry2x32(key, hi32(count), lo32(count))
//   bits = b1 ^ b2     (jax/_src/prng.py, bit_width==32 path — XOR fold)
__device__ __forceinline__ uint32_t jax_bits(uint32_t p) {
  uint32_t o0, o1;
  threefry(0u, p, o0, o1);
  return o0 ^ o1;
}

// JAX uniform(minval=1e-10, maxval=1.0): f = bits>>9 | one; u = max(1e-10, f + 1e-10)
__device__ __forceinline__ float bits_to_gumbel(uint32_t bits) {
  float f = __uint_as_float((bits >> 9) | 0x3F800000u) - 1.0f;
  float u = fmaxf(1e-10f, f + 1e-10f);
  return -logf(-logf(u));
}

__device__ __forceinline__ float gelu_exact(float x) {
  return 0.5f * x * (1.0f + erff(x * 0.70710678118654752440f));
}

// MLP 1->16->8->2, log_softmax, add gumbel noise, hard argmax (first-max wins).
__device__ __forceinline__ float hard_bit(float c, uint32_t q,
    const float* __restrict__ sW1, const float* __restrict__ sb1,
    const float* __restrict__ sW2, const float* __restrict__ sb2,
    const float* __restrict__ sW3, const float* __restrict__ sb3)
{
  float h1[16];
#pragma unroll
  for (int j = 0; j < 16; j++) h1[j] = gelu_exact(fmaf(c, sW1[j], sb1[j]));
  float h2[8];
#pragma unroll
  for (int k = 0; k < 8; k++) {
    float a = sb2[k];
#pragma unroll
    for (int j = 0; j < 16; j++) a = fmaf(h1[j], sW2[j * 8 + k], a);
    h2[k] = gelu_exact(a);
  }
  float z0 = sb3[0], z1 = sb3[1];
#pragma unroll
  for (int k = 0; k < 8; k++) {
    z0 = fmaf(h2[k], sW3[2 * k + 0], z0);
    z1 = fmaf(h2[k], sW3[2 * k + 1], z1);
  }
  // log_softmax (same form as jax.nn.log_softmax)
  float mx = fmaxf(z0, z1);
  float s0 = z0 - mx, s1 = z1 - mx;
  float lse = logf(expf(s0) + expf(s1));
  float l0 = s0 - lse, l1 = s1 - lse;
  // gumbel noise at flat positions p0=2q, p1=2q+1 of shape [NB, NS*NS, 2]
  float g0 = bits_to_gumbel(jax_bits(2u * q));
  float g1 = bits_to_gumbel(jax_bits(2u * q + 1u));
  return (l0 + g0 >= l1 + g1) ? 1.0f : 0.0f;
}

// ---------------------------------------------------------------------------
// Kernel 1: adjacency bits.  corr = fm[b] @ fm[b]^T (tiled 64x64x16), then
// per-entry MLP+gumbel epilogue; diag forced to 1.  Writes g_adj in {0,1}.
// ---------------------------------------------------------------------------
__global__ void __launch_bounds__(256) adj_kernel(
    const float* __restrict__ fm,
    const float* __restrict__ W1, const float* __restrict__ b1,
    const float* __restrict__ W2, const float* __restrict__ b2,
    const float* __restrict__ W3, const float* __restrict__ b3)
{
  __shared__ float As[16][64];
  __shared__ float Bs[16][64];
  __shared__ float sW1[16], sb1[16], sW2[128], sb2[8], sW3[16], sb3[2];

  const int tid = threadIdx.x;
  const int b  = blockIdx.z;
  const int s0 = blockIdx.y * 64;
  const int t0 = blockIdx.x * 64;

  if (tid < 16)        sW1[tid]       = W1[tid];
  else if (tid < 32)   sb1[tid - 16]  = b1[tid - 16];
  else if (tid < 160)  sW2[tid - 32]  = W2[tid - 32];
  else if (tid < 168)  sb2[tid - 160] = b2[tid - 160];
  else if (tid < 184)  sW3[tid - 168] = W3[tid - 168];
  else if (tid < 186)  sb3[tid - 184] = b3[tid - 184];

  const float* A = fm + (size_t)b * NS * NL;
  const int lr = tid >> 2;           // 0..63
  const int lc = (tid & 3) << 2;     // 0,4,8,12
  const int ty = tid >> 4;           // 0..15
  const int tx = tid & 15;           // 0..15

  float acc[4][4];
#pragma unroll
  for (int i = 0; i < 4; i++)
#pragma unroll
    for (int j = 0; j < 4; j++) acc[i][j] = 0.f;

  for (int k0 = 0; k0 < NL; k0 += 16) {
    float4 av = *reinterpret_cast<const float4*>(A + (s0 + lr) * NL + k0 + lc);
    float4 bv = *reinterpret_cast<const float4*>(A + (t0 + lr) * NL + k0 + lc);
    __syncthreads();
    As[lc + 0][lr] = av.x; As[lc + 1][lr] = av.y; As[lc + 2][lr] = av.z; As[lc + 3][lr] = av.w;
    Bs[lc + 0][lr] = bv.x; Bs[lc + 1][lr] = bv.y; Bs[lc + 2][lr] = bv.z; Bs[lc + 3][lr] = bv.w;
    __syncthreads();
#pragma unroll
    for (int k = 0; k < 16; k++) {
      float4 a  = *reinterpret_cast<const float4*>(&As[k][ty << 2]);
      float4 bb = *reinterpret_cast<const float4*>(&Bs[k][tx << 2]);
      acc[0][0] = fmaf(a.x, bb.x, acc[0][0]); acc[0][1] = fmaf(a.x, bb.y, acc[0][1]);
      acc[0][2] = fmaf(a.x, bb.z, acc[0][2]); acc[0][3] = fmaf(a.x, bb.w, acc[0][3]);
      acc[1][0] = fmaf(a.y, bb.x, acc[1][0]); acc[1][1] = fmaf(a.y, bb.y, acc[1][1]);
      acc[1][2] = fmaf(a.y, bb.z, acc[1][2]); acc[1][3] = fmaf(a.y, bb.w, acc[1][3]);
      acc[2][0] = fmaf(a.z, bb.x, acc[2][0]); acc[2][1] = fmaf(a.z, bb.y, acc[2][1]);
      acc[2][2] = fmaf(a.z, bb.z, acc[2][2]); acc[2][3] = fmaf(a.z, bb.w, acc[2][3]);
      acc[3][0] = fmaf(a.w, bb.x, acc[3][0]); acc[3][1] = fmaf(a.w, bb.y, acc[3][1]);
      acc[3][2] = fmaf(a.w, bb.z, acc[3][2]); acc[3][3] = fmaf(a.w, bb.w, acc[3][3]);
    }
  }

#pragma unroll
  for (int i = 0; i < 4; i++) {
    int s = s0 + (ty << 2) + i;
#pragma unroll
    for (int j = 0; j < 4; j++) {
      int t = t0 + (tx << 2) + j;
      uint32_t q = ((uint32_t)b << 16) | ((uint32_t)s << 8) | (uint32_t)t;
      float bit;
      if (s == t) bit = 1.0f;  // identity mix forces exact 1 on the diagonal
      else bit = hard_bit(acc[i][j], q, sW1, sb1, sW2, sb2, sW3, sb3);
      g_adj[q] = bit;
    }
  }
}

// ---------------------------------------------------------------------------
// Kernel 2: inverse degree per row (exact: {0,1} entries sum exactly)
// ---------------------------------------------------------------------------
__global__ void __launch_bounds__(256) invdeg_kernel() {
  int warp = (blockIdx.x * blockDim.x + threadIdx.x) >> 5;
  int lane = threadIdx.x & 31;
  if (warp >= NB * NS) return;
  const float* row = g_adj + (size_t)warp * NS;
  float s = 0.f;
#pragma unroll
  for (int t = lane; t < NS; t += 32) s += row[t];
#pragma unroll
  for (int o = 16; o; o >>= 1) s += __shfl_xor_sync(0xFFFFFFFFu, s, o);
  if (lane == 0) g_invdeg[warp] = 1.0f / s;
}

// ---------------------------------------------------------------------------
// Kernel 3: Y[bc] = invdeg * (adj[b] @ F[bc])     (128 batched 256^3 GEMMs)
// ---------------------------------------------------------------------------
__global__ void __launch_bounds__(256) prop_kernel(const float* __restrict__ features) {
  __shared__ float As[16][64];
  __shared__ float Bs[16][64];
  const int tid = threadIdx.x;
  const int bc = blockIdx.z;         // 0..127
  const int b  = bc >> 2;
  const int s0 = blockIdx.y * 64;
  const int d0 = blockIdx.x * 64;

  const float* A  = g_adj + (size_t)b * NS * NS;
  const float* Bm = features + (size_t)bc * NS * NDIN;

  const int lr = tid >> 2, lc = (tid & 3) << 2;        // A tile (transpose-store)
  const int br = tid >> 4, bn = (tid & 15) << 2;       // B tile (direct)
  const int ty = tid >> 4, tx = tid & 15;

  float acc[4][4];
#pragma unroll
  for (int i = 0; i < 4; i++)
#pragma unroll
    for (int j = 0; j < 4; j++) acc[i][j] = 0.f;

  for (int k0 = 0; k0 < NS; k0 += 16) {
    float4 av = *reinterpret_cast<const float4*>(A  + (s0 + lr) * NS  + k0 + lc);
    float4 bv = *reinterpret_cast<const float4*>(Bm + (k0 + br) * NDIN + d0 + bn);
    __syncthreads();
    As[lc + 0][lr] = av.x; As[lc + 1][lr] = av.y; As[lc + 2][lr] = av.z; As[lc + 3][lr] = av.w;
    *reinterpret_cast<float4*>(&Bs[br][bn]) = bv;
    __syncthreads();
#pragma unroll
    for (int k = 0; k < 16; k++) {
      float4 a  = *reinterpret_cast<const float4*>(&As[k][ty << 2]);
      float4 bb = *reinterpret_cast<const float4*>(&Bs[k][tx << 2]);
      acc[0][0] = fmaf(a.x, bb.x, acc[0][0]); acc[0][1] = fmaf(a.x, bb.y, acc[0][1]);
      acc[0][2] = fmaf(a.x, bb.z, acc[0][2]); acc[0][3] = fmaf(a.x, bb.w, acc[0][3]);
      acc[1][0] = fmaf(a.y, bb.x, acc[1][0]); acc[1][1] = fmaf(a.y, bb.y, acc[1][1]);
      acc[1][2] = fmaf(a.y, bb.z, acc[1][2]); acc[1][3] = fmaf(a.y, bb.w, acc[1][3]);
      acc[2][0] = fmaf(a.z, bb.x, acc[2][0]); acc[2][1] = fmaf(a.z, bb.y, acc[2][1]);
      acc[2][2] = fmaf(a.z, bb.z, acc[2][2]); acc[2][3] = fmaf(a.z, bb.w, acc[2][3]);
      acc[3][0] = fmaf(a.w, bb.x, acc[3][0]); acc[3][1] = fmaf(a.w, bb.y, acc[3][1]);
      acc[3][2] = fmaf(a.w, bb.z, acc[3][2]); acc[3][3] = fmaf(a.w, bb.w, acc[3][3]);
    }
  }

#pragma unroll
  for (int i = 0; i < 4; i++) {
    int s = s0 + (ty << 2) + i;
    float sc = g_invdeg[b * NS + s];
    float4 v = make_float4(sc * acc[i][0], sc * acc[i][1], sc * acc[i][2], sc * acc[i][3]);
    *reinterpret_cast<float4*>(&g_Y[((size_t)bc * NS + s) * NDIN + d0 + (tx << 2)]) = v;
  }
}

// ---------------------------------------------------------------------------
// Kernel 4: out = Y @ Wl + bl     (single 32768 x 256 x 256 GEMM)
// ---------------------------------------------------------------------------
__global__ void __launch_bounds__(256) out_kernel(const float* __restrict__ Wl,
                                                  const float* __restrict__ bl,
                                                  float* __restrict__ out) {
  __shared__ float As[16][64];
  __shared__ float Bs[16][64];
  const int tid = threadIdx.x;
  const int m0 = blockIdx.y * 64;
  const int n0 = blockIdx.x * 64;

  const int lr = tid >> 2, lc = (tid & 3) << 2;
  const int br = tid >> 4, bn = (tid & 15) << 2;
  const int ty = tid >> 4, tx = tid & 15;

  float acc[4][4];
#pragma unroll
  for (int i = 0; i < 4; i++)
#pragma unroll
    for (int j = 0; j < 4; j++) acc[i][j] = 0.f;

  for (int k0 = 0; k0 < NDIN; k0 += 16) {
    float4 av = *reinterpret_cast<const float4*>(&g_Y[(size_t)(m0 + lr) * NDIN + k0 + lc]);
    float4 bv = *reinterpret_cast<const float4*>(Wl + (k0 + br) * NDOUT + n0 + bn);
    __syncthreads();
    As[lc + 0][lr] = av.x; As[lc + 1][lr] = av.y; As[lc + 2][lr] = av.z; As[lc + 3][lr] = av.w;
    *reinterpret_cast<float4*>(&Bs[br][bn]) = bv;
    __syncthreads();
#pragma unroll
    for (int k = 0; k < 16; k++) {
      float4 a  = *reinterpret_cast<const float4*>(&As[k][ty << 2]);
      float4 bb = *reinterpret_cast<const float4*>(&Bs[k][tx << 2]);
      acc[0][0] = fmaf(a.x, bb.x, acc[0][0]); acc[0][1] = fmaf(a.x, bb.y, acc[0][1]);
      acc[0][2] = fmaf(a.x, bb.z, acc[0][2]); acc[0][3] = fmaf(a.x, bb.w, acc[0][3]);
      acc[1][0] = fmaf(a.y, bb.x, acc[1][0]); acc[1][1] = fmaf(a.y, bb.y, acc[1][1]);
      acc[1][2] = fmaf(a.y, bb.z, acc[1][2]); acc[1][3] = fmaf(a.y, bb.w, acc[1][3]);
      acc[2][0] = fmaf(a.z, bb.x, acc[2][0]); acc[2][1] = fmaf(a.z, bb.y, acc[2][1]);
      acc[2][2] = fmaf(a.z, bb.z, acc[2][2]); acc[2][3] = fmaf(a.z, bb.w, acc[2][3]);
      acc[3][0] = fmaf(a.w, bb.x, acc[3][0]); acc[3][1] = fmaf(a.w, bb.y, acc[3][1]);
      acc[3][2] = fmaf(a.w, bb.z, acc[3][2]); acc[3][3] = fmaf(a.w, bb.w, acc[3][3]);
    }
  }

  float4 bias = *reinterpret_cast<const float4*>(bl + n0 + (tx << 2));
#pragma unroll
  for (int i = 0; i < 4; i++) {
    int m = m0 + (ty << 2) + i;
    float4 v = make_float4(acc[i][0] + bias.x, acc[i][1] + bias.y,
                           acc[i][2] + bias.z, acc[i][3] + bias.w);
    *reinterpret_cast<float4*>(&out[(size_t)m * NDOUT + n0 + (tx << 2)]) = v;
  }
}

// ---------------------------------------------------------------------------
extern "C" void kernel_launch(void* const* d_in, const int* in_sizes, int n_in,
                              void* d_out, int out_size) {
  // Bind by element count where unambiguous (robust to metadata ordering):
  //   features 8388608, features_mean 2097152, W2 128, b2 8, b3 2, Wl 65536, bl 256.
  //   The three size-16 tensors appear in order W1, b1, W3.
  const float *features = 0, *fm = 0, *W1 = 0, *b1 = 0, *W2 = 0, *b2 = 0,
              *W3 = 0, *b3 = 0, *Wl = 0, *bl = 0;
  int n16 = 0;
  for (int i = 0; i < n_in; i++) {
    const float* p = (const float*)d_in[i];
    switch (in_sizes[i]) {
      case 8388608: features = p; break;
      case 2097152: fm = p; break;
      case 128:     W2 = p; break;
      case 8:       b2 = p; break;
      case 2:       b3 = p; break;
      case 65536:   Wl = p; break;
      case 256:     bl = p; break;
      case 16:
        if (n16 == 0) W1 = p; else if (n16 == 1) b1 = p; else W3 = p;
        n16++; break;
      default: break;
    }
  }
  float* out = (float*)d_out;

  adj_kernel<<<dim3(4, 4, 32), 256>>>(fm, W1, b1, W2, b2, W3, b3);
  invdeg_kernel<<<(NB * NS) / 8, 256>>>();
  prop_kernel<<<dim3(4, 4, 128), 256>>>(features);
  out_kernel<<<dim3(4, 512, 1), 256>>>(Wl, bl, out);
}

// round 7
// speedup vs baseline: 1.0377x; 1.0377x over previous
#include <cuda_runtime.h>
#include <stdint.h>

#define NB 32
#define NC 4
#define NS 256
#define NL 256
#define NDIN 256
#define NDOUT 256

// Scratch (static device globals: allocation-free per harness rules)
__device__ float g_adj[NB * NS * NS];                 // 8 MB, entries exactly {0,1}
__device__ float g_invdeg[NB * NS];                   // 32 KB
__device__ float g_Y[(size_t)NB * NC * NS * NDIN];    // 33.5 MB

// ---------------------------------------------------------------------------
// Threefry-2x32 with key = (0, 42)  (jax.random.key(42))
// ---------------------------------------------------------------------------
__device__ __forceinline__ void threefry(uint32_t x0, uint32_t x1,
                                         uint32_t& o0, uint32_t& o1) {
  const uint32_t ks0 = 0u;
  const uint32_t ks1 = 42u;
  const uint32_t ks2 = 0u ^ 42u ^ 0x1BD11BDAu;
  x0 += ks0; x1 += ks1;
#define TF_R(r) { x0 += x1; x1 = __funnelshift_l(x1, x1, (r)); x1 ^= x0; }
  TF_R(13) TF_R(15) TF_R(26) TF_R(6)
  x0 += ks1; x1 += ks2 + 1u;
  TF_R(17) TF_R(29) TF_R(16) TF_R(24)
  x0 += ks2; x1 += ks0 + 2u;
  TF_R(13) TF_R(15) TF_R(26) TF_R(6)
  x0 += ks0; x1 += ks1 + 3u;
  TF_R(17) TF_R(29) TF_R(16) TF_R(24)
  x0 += ks1; x1 += ks2 + 4u;
  TF_R(13) TF_R(15) TF_R(26) TF_R(6)
  x0 += ks2; x1 += ks0 + 5u;
#undef TF_R
  o0 = x0; o1 = x1;
}

// Partitionable threefry (JAX >= 0.4.36 default), 32-bit draws: XOR fold.
__device__ __forceinline__ uint32_t jax_bits(uint32_t p) {
  uint32_t o0, o1;
  threefry(0u, p, o0, o1);
  return o0 ^ o1;
}

// JAX uniform(minval=1e-10, maxval=1.0): f = bits>>9 | one; u = max(1e-10, f + 1e-10)
__device__ __forceinline__ float bits_to_gumbel(uint32_t bits) {
  float f = __uint_as_float((bits >> 9) | 0x3F800000u) - 1.0f;
  float u = fmaxf(1e-10f, f + 1e-10f);
  return -logf(-logf(u));
}

__device__ __forceinline__ float gelu_exact(float x) {
  return 0.5f * x * (1.0f + erff(x * 0.70710678118654752440f));
}

// MLP 1->16->8->2, log_softmax, add gumbel noise, hard argmax (first-max wins).
__device__ __forceinline__ float hard_bit(float c, uint32_t q,
    const float* __restrict__ sW1, const float* __restrict__ sb1,
    const float* __restrict__ sW2, const float* __restrict__ sb2,
    const float* __restrict__ sW3, const float* __restrict__ sb3)
{
  float h1[16];
#pragma unroll
  for (int j = 0; j < 16; j++) h1[j] = gelu_exact(fmaf(c, sW1[j], sb1[j]));
  float h2[8];
#pragma unroll
  for (int k = 0; k < 8; k++) {
    float a = sb2[k];
#pragma unroll
    for (int j = 0; j < 16; j++) a = fmaf(h1[j], sW2[j * 8 + k], a);
    h2[k] = gelu_exact(a);
  }
  float z0 = sb3[0], z1 = sb3[1];
#pragma unroll
  for (int k = 0; k < 8; k++) {
    z0 = fmaf(h2[k], sW3[2 * k + 0], z0);
    z1 = fmaf(h2[k], sW3[2 * k + 1], z1);
  }
  // log_softmax (same form as jax.nn.log_softmax)
  float mx = fmaxf(z0, z1);
  float s0 = z0 - mx, s1 = z1 - mx;
  float lse = logf(expf(s0) + expf(s1));
  float l0 = s0 - lse, l1 = s1 - lse;
  float g0 = bits_to_gumbel(jax_bits(2u * q));
  float g1 = bits_to_gumbel(jax_bits(2u * q + 1u));
  return (l0 + g0 >= l1 + g1) ? 1.0f : 0.0f;
}

// ---------------------------------------------------------------------------
// Kernel 1: adjacency bits (64x64 GEMM tile + MLP/gumbel epilogue) — epilogue
// is ALU/MUFU bound, so the modest GEMM tile is fine and keeps 512 blocks live.
// ---------------------------------------------------------------------------
__global__ void __launch_bounds__(256) adj_kernel(
    const float* __restrict__ fm,
    const float* __restrict__ W1, const float* __restrict__ b1,
    const float* __restrict__ W2, const float* __restrict__ b2,
    const float* __restrict__ W3, const float* __restrict__ b3)
{
  __shared__ float As[16][64];
  __shared__ float Bs[16][64];
  __shared__ float sW1[16], sb1[16], sW2[128], sb2[8], sW3[16], sb3[2];

  const int tid = threadIdx.x;
  const int b  = blockIdx.z;
  const int s0 = blockIdx.y * 64;
  const int t0 = blockIdx.x * 64;

  if (tid < 16)        sW1[tid]       = W1[tid];
  else if (tid < 32)   sb1[tid - 16]  = b1[tid - 16];
  else if (tid < 160)  sW2[tid - 32]  = W2[tid - 32];
  else if (tid < 168)  sb2[tid - 160] = b2[tid - 160];
  else if (tid < 184)  sW3[tid - 168] = W3[tid - 168];
  else if (tid < 186)  sb3[tid - 184] = b3[tid - 184];

  const float* A = fm + (size_t)b * NS * NL;
  const int lr = tid >> 2;           // 0..63
  const int lc = (tid & 3) << 2;     // 0,4,8,12
  const int ty = tid >> 4;           // 0..15
  const int tx = tid & 15;           // 0..15

  float acc[4][4];
#pragma unroll
  for (int i = 0; i < 4; i++)
#pragma unroll
    for (int j = 0; j < 4; j++) acc[i][j] = 0.f;

  for (int k0 = 0; k0 < NL; k0 += 16) {
    float4 av = *reinterpret_cast<const float4*>(A + (s0 + lr) * NL + k0 + lc);
    float4 bv = *reinterpret_cast<const float4*>(A + (t0 + lr) * NL + k0 + lc);
    __syncthreads();
    As[lc + 0][lr] = av.x; As[lc + 1][lr] = av.y; As[lc + 2][lr] = av.z; As[lc + 3][lr] = av.w;
    Bs[lc + 0][lr] = bv.x; Bs[lc + 1][lr] = bv.y; Bs[lc + 2][lr] = bv.z; Bs[lc + 3][lr] = bv.w;
    __syncthreads();
#pragma unroll
    for (int k = 0; k < 16; k++) {
      float4 a  = *reinterpret_cast<const float4*>(&As[k][ty << 2]);
      float4 bb = *reinterpret_cast<const float4*>(&Bs[k][tx << 2]);
      acc[0][0] = fmaf(a.x, bb.x, acc[0][0]); acc[0][1] = fmaf(a.x, bb.y, acc[0][1]);
      acc[0][2] = fmaf(a.x, bb.z, acc[0][2]); acc[0][3] = fmaf(a.x, bb.w, acc[0][3]);
      acc[1][0] = fmaf(a.y, bb.x, acc[1][0]); acc[1][1] = fmaf(a.y, bb.y, acc[1][1]);
      acc[1][2] = fmaf(a.y, bb.z, acc[1][2]); acc[1][3] = fmaf(a.y, bb.w, acc[1][3]);
      acc[2][0] = fmaf(a.z, bb.x, acc[2][0]); acc[2][1] = fmaf(a.z, bb.y, acc[2][1]);
      acc[2][2] = fmaf(a.z, bb.z, acc[2][2]); acc[2][3] = fmaf(a.z, bb.w, acc[2][3]);
      acc[3][0] = fmaf(a.w, bb.x, acc[3][0]); acc[3][1] = fmaf(a.w, bb.y, acc[3][1]);
      acc[3][2] = fmaf(a.w, bb.z, acc[3][2]); acc[3][3] = fmaf(a.w, bb.w, acc[3][3]);
    }
  }

#pragma unroll
  for (int i = 0; i < 4; i++) {
    int s = s0 + (ty << 2) + i;
#pragma unroll
    for (int j = 0; j < 4; j++) {
      int t = t0 + (tx << 2) + j;
      uint32_t q = ((uint32_t)b << 16) | ((uint32_t)s << 8) | (uint32_t)t;
      float bit;
      if (s == t) bit = 1.0f;
      else bit = hard_bit(acc[i][j], q, sW1, sb1, sW2, sb2, sW3, sb3);
      g_adj[q] = bit;
    }
  }
}

// ---------------------------------------------------------------------------
// Kernel 2: inverse degree per row (exact: {0,1} entries sum exactly)
// ---------------------------------------------------------------------------
__global__ void __launch_bounds__(256) invdeg_kernel() {
  int warp = (blockIdx.x * blockDim.x + threadIdx.x) >> 5;
  int lane = threadIdx.x & 31;
  if (warp >= NB * NS) return;
  const float* row = g_adj + (size_t)warp * NS;
  float s = 0.f;
#pragma unroll
  for (int t = lane; t < NS; t += 32) s += row[t];
#pragma unroll
  for (int o = 16; o; o >>= 1) s += __shfl_xor_sync(0xFFFFFFFFu, s, o);
  if (lane == 0) g_invdeg[warp] = 1.0f / s;
}

// ---------------------------------------------------------------------------
// 128x128x8 double-buffered fp32 GEMM core (8x8 micro-tile, 256 threads):
// 1 B smem per FMA — crossbar-balanced, ~2x the fma throughput of 64x64.
// ---------------------------------------------------------------------------
struct Gemm128Frag {
  float acc[8][8];
};

// Kernel 3: Y[bc] = invdeg * (adj[b] @ F[bc])
__global__ void __launch_bounds__(256) prop_kernel(const float* __restrict__ features) {
  __shared__ float As[2][8][128];   // [buf][k][m]  (transposed store)
  __shared__ float Bs[2][8][128];   // [buf][k][n]

  const int tid = threadIdx.x;
  const int bc = blockIdx.z;         // 0..127
  const int b  = bc >> 2;
  const int s0 = blockIdx.y * 128;
  const int d0 = blockIdx.x * 128;

  const float* A  = g_adj + (size_t)b * NS * NS;
  const float* Bm = features + (size_t)bc * NS * NDIN;

  // load maps
  const int ar = tid >> 1;               // 0..127  (A row within tile)
  const int ac = (tid & 1) << 2;         // 0 or 4  (A col group)
  const int brow = tid >> 5;             // 0..7    (B row = k)
  const int bcol = (tid & 31) << 2;      // 0..124  (B col group)
  // compute maps
  const int ty = tid >> 4;               // 0..15 -> rows ty*8..
  const int tx = tid & 15;               // 0..15 -> cols tx*8..

  float acc[8][8];
#pragma unroll
  for (int i = 0; i < 8; i++)
#pragma unroll
    for (int j = 0; j < 8; j++) acc[i][j] = 0.f;

  // preload tile 0
  float4 av = *reinterpret_cast<const float4*>(A  + (s0 + ar) * NS + ac);
  float4 bv = *reinterpret_cast<const float4*>(Bm + brow * NDIN + d0 + bcol);
  As[0][ac + 0][ar] = av.x; As[0][ac + 1][ar] = av.y;
  As[0][ac + 2][ar] = av.z; As[0][ac + 3][ar] = av.w;
  *reinterpret_cast<float4*>(&Bs[0][brow][bcol]) = bv;
  __syncthreads();

  const int NK = NS / 8;  // 32
  for (int kt = 0; kt < NK; kt++) {
    const int cur = kt & 1;
    if (kt + 1 < NK) {
      int k0 = (kt + 1) * 8;
      av = *reinterpret_cast<const float4*>(A  + (s0 + ar) * NS + k0 + ac);
      bv = *reinterpret_cast<const float4*>(Bm + (k0 + brow) * NDIN + d0 + bcol);
    }
#pragma unroll
    for (int k = 0; k < 8; k++) {
      float4 a0 = *reinterpret_cast<const float4*>(&As[cur][k][ty * 8 + 0]);
      float4 a1 = *reinterpret_cast<const float4*>(&As[cur][k][ty * 8 + 4]);
      float4 b0 = *reinterpret_cast<const float4*>(&Bs[cur][k][tx * 8 + 0]);
      float4 b1 = *reinterpret_cast<const float4*>(&Bs[cur][k][tx * 8 + 4]);
      float ar_[8] = {a0.x, a0.y, a0.z, a0.w, a1.x, a1.y, a1.z, a1.w};
      float br_[8] = {b0.x, b0.y, b0.z, b0.w, b1.x, b1.y, b1.z, b1.w};
#pragma unroll
      for (int i = 0; i < 8; i++)
#pragma unroll
        for (int j = 0; j < 8; j++)
          acc[i][j] = fmaf(ar_[i], br_[j], acc[i][j]);
    }
    if (kt + 1 < NK) {
      const int nxt = 1 - cur;
      As[nxt][ac + 0][ar] = av.x; As[nxt][ac + 1][ar] = av.y;
      As[nxt][ac + 2][ar] = av.z; As[nxt][ac + 3][ar] = av.w;
      *reinterpret_cast<float4*>(&Bs[nxt][brow][bcol]) = bv;
      __syncthreads();
    }
  }

#pragma unroll
  for (int i = 0; i < 8; i++) {
    int s = s0 + ty * 8 + i;
    float sc = g_invdeg[b * NS + s];
    float4 v0 = make_float4(sc * acc[i][0], sc * acc[i][1], sc * acc[i][2], sc * acc[i][3]);
    float4 v1 = make_float4(sc * acc[i][4], sc * acc[i][5], sc * acc[i][6], sc * acc[i][7]);
    float* dst = &g_Y[((size_t)bc * NS + s) * NDIN + d0 + tx * 8];
    *reinterpret_cast<float4*>(dst + 0) = v0;
    *reinterpret_cast<float4*>(dst + 4) = v1;
  }
}

// Kernel 4: out = Y @ Wl + bl    (32768 x 256 x 256)
__global__ void __launch_bounds__(256) out_kernel(const float* __restrict__ Wl,
                                                  const float* __restrict__ bl,
                                                  float* __restrict__ out) {
  __shared__ float As[2][8][128];
  __shared__ float Bs[2][8][128];

  const int tid = threadIdx.x;
  const int m0 = blockIdx.y * 128;
  const int n0 = blockIdx.x * 128;

  const int ar = tid >> 1;
  const int ac = (tid & 1) << 2;
  const int brow = tid >> 5;
  const int bcol = (tid & 31) << 2;
  const int ty = tid >> 4;
  const int tx = tid & 15;

  float acc[8][8];
#pragma unroll
  for (int i = 0; i < 8; i++)
#pragma unroll
    for (int j = 0; j < 8; j++) acc[i][j] = 0.f;

  float4 av = *reinterpret_cast<const float4*>(&g_Y[(size_t)(m0 + ar) * NDIN + ac]);
  float4 bv = *reinterpret_cast<const float4*>(Wl + brow * NDOUT + n0 + bcol);
  As[0][ac + 0][ar] = av.x; As[0][ac + 1][ar] = av.y;
  As[0][ac + 2][ar] = av.z; As[0][ac + 3][ar] = av.w;
  *reinterpret_cast<float4*>(&Bs[0][brow][bcol]) = bv;
  __syncthreads();

  const int NK = NDIN / 8;  // 32
  for (int kt = 0; kt < NK; kt++) {
    const int cur = kt & 1;
    if (kt + 1 < NK) {
      int k0 = (kt + 1) * 8;
      av = *reinterpret_cast<const float4*>(&g_Y[(size_t)(m0 + ar) * NDIN + k0 + ac]);
      bv = *reinterpret_cast<const float4*>(Wl + (k0 + brow) * NDOUT + n0 + bcol);
    }
#pragma unroll
    for (int k = 0; k < 8; k++) {
      float4 a0 = *reinterpret_cast<const float4*>(&As[cur][k][ty * 8 + 0]);
      float4 a1 = *reinterpret_cast<const float4*>(&As[cur][k][ty * 8 + 4]);
      float4 b0 = *reinterpret_cast<const float4*>(&Bs[cur][k][tx * 8 + 0]);
      float4 b1 = *reinterpret_cast<const float4*>(&Bs[cur][k][tx * 8 + 4]);
      float ar_[8] = {a0.x, a0.y, a0.z, a0.w, a1.x, a1.y, a1.z, a1.w};
      float br_[8] = {b0.x, b0.y, b0.z, b0.w, b1.x, b1.y, b1.z, b1.w};
#pragma unroll
      for (int i = 0; i < 8; i++)
#pragma unroll
        for (int j = 0; j < 8; j++)
          acc[i][j] = fmaf(ar_[i], br_[j], acc[i][j]);
    }
    if (kt + 1 < NK) {
      const int nxt = 1 - cur;
      As[nxt][ac + 0][ar] = av.x; As[nxt][ac + 1][ar] = av.y;
      As[nxt][ac + 2][ar] = av.z; As[nxt][ac + 3][ar] = av.w;
      *reinterpret_cast<float4*>(&Bs[nxt][brow][bcol]) = bv;
      __syncthreads();
    }
  }

  float4 bias0 = *reinterpret_cast<const float4*>(bl + n0 + tx * 8 + 0);
  float4 bias1 = *reinterpret_cast<const float4*>(bl + n0 + tx * 8 + 4);
#pragma unroll
  for (int i = 0; i < 8; i++) {
    int m = m0 + ty * 8 + i;
    float4 v0 = make_float4(acc[i][0] + bias0.x, acc[i][1] + bias0.y,
                            acc[i][2] + bias0.z, acc[i][3] + bias0.w);
    float4 v1 = make_float4(acc[i][4] + bias1.x, acc[i][5] + bias1.y,
                            acc[i][6] + bias1.z, acc[i][7] + bias1.w);
    float* dst = &out[(size_t)m * NDOUT + n0 + tx * 8];
    *reinterpret_cast<float4*>(dst + 0) = v0;
    *reinterpret_cast<float4*>(dst + 4) = v1;
  }
}

// ---------------------------------------------------------------------------
extern "C" void kernel_launch(void* const* d_in, const int* in_sizes, int n_in,
                              void* d_out, int out_size) {
  const float *features = 0, *fm = 0, *W1 = 0, *b1 = 0, *W2 = 0, *b2 = 0,
              *W3 = 0, *b3 = 0, *Wl = 0, *bl = 0;
  int n16 = 0;
  for (int i = 0; i < n_in; i++) {
    const float* p = (const float*)d_in[i];
    switch (in_sizes[i]) {
      case 8388608: features = p; break;
      case 2097152: fm = p; break;
      case 128:     W2 = p; break;
      case 8:       b2 = p; break;
      case 2:       b3 = p; break;
      case 65536:   Wl = p; break;
      case 256:     bl = p; break;
      case 16:
        if (n16 == 0) W1 = p; else if (n16 == 1) b1 = p; else W3 = p;
        n16++; break;
      default: break;
    }
  }
  float* out = (float*)d_out;

  adj_kernel<<<dim3(4, 4, 32), 256>>>(fm, W1, b1, W2, b2, W3, b3);
  invdeg_kernel<<<(NB * NS) / 8, 256>>>();
  prop_kernel<<<dim3(2, 2, 128), 256>>>(features);
  out_kernel<<<dim3(2, 256, 1), 256>>>(Wl, bl, out);
}

// round 9
// speedup vs baseline: 1.4566x; 1.4036x over previous
#include <cuda_runtime.h>
#include <stdint.h>

#define NB 32
#define NC 4
#define NS 256
#define NL 256
#define NDIN 256
#define NDOUT 256

#define TAB_N 16384               // intervals; knots = TAB_N+1; c = -128 + i/64
#define TAB_SCALE 64.0f
#define TAB_H (1.0f / 64.0f)

// Scratch (static device globals: allocation-free per harness rules)
__device__ float g_adj[NB * NS * NS];                 // 8 MB, entries exactly {0,1}
__device__ float g_invdeg[NB * NS];                   // 32 KB
__device__ float g_Y[(size_t)NB * NC * NS * NDIN];    // 33.5 MB
__device__ float2 g_tab[TAB_N + 1];                   // (f, df) Hermite knots, 128 KB

// ---------------------------------------------------------------------------
// Threefry-2x32 with key = (0, 42)  (jax.random.key(42))
// ---------------------------------------------------------------------------
__device__ __forceinline__ void threefry(uint32_t x0, uint32_t x1,
                                         uint32_t& o0, uint32_t& o1) {
  const uint32_t ks0 = 0u;
  const uint32_t ks1 = 42u;
  const uint32_t ks2 = 0u ^ 42u ^ 0x1BD11BDAu;
  x0 += ks0; x1 += ks1;
#define TF_R(r) { x0 += x1; x1 = __funnelshift_l(x1, x1, (r)); x1 ^= x0; }
  TF_R(13) TF_R(15) TF_R(26) TF_R(6)
  x0 += ks1; x1 += ks2 + 1u;
  TF_R(17) TF_R(29) TF_R(16) TF_R(24)
  x0 += ks2; x1 += ks0 + 2u;
  TF_R(13) TF_R(15) TF_R(26) TF_R(6)
  x0 += ks0; x1 += ks1 + 3u;
  TF_R(17) TF_R(29) TF_R(16) TF_R(24)
  x0 += ks1; x1 += ks2 + 4u;
  TF_R(13) TF_R(15) TF_R(26) TF_R(6)
  x0 += ks2; x1 += ks0 + 5u;
#undef TF_R
  o0 = x0; o1 = x1;
}

// Partitionable threefry (JAX >= 0.4.36 default), 32-bit draws: XOR fold.
__device__ __forceinline__ uint32_t jax_bits(uint32_t p) {
  uint32_t o0, o1;
  threefry(0u, p, o0, o1);
  return o0 ^ o1;
}

// JAX uniform(minval=1e-10, maxval=1.0): f = bits>>9 | one; u = max(1e-10, f + 1e-10)
__device__ __forceinline__ float bits_to_gumbel(uint32_t bits) {
  float f = __uint_as_float((bits >> 9) | 0x3F800000u) - 1.0f;
  float u = fmaxf(1e-10f, f + 1e-10f);
  return -logf(-logf(u));
}

__device__ __forceinline__ float gelu_exact(float x) {
  return 0.5f * x * (1.0f + erff(x * 0.70710678118654752440f));
}

// ---------------------------------------------------------------------------
// Exact MLP margin z0 - z1 (same fma ordering as the R6 passing kernel).
// ---------------------------------------------------------------------------
__device__ __forceinline__ void mlp_z(float c,
    const float* __restrict__ W1, const float* __restrict__ b1,
    const float* __restrict__ W2, const float* __restrict__ b2,
    const float* __restrict__ W3, const float* __restrict__ b3,
    float& z0, float& z1)
{
  float h1[16];
#pragma unroll
  for (int j = 0; j < 16; j++) h1[j] = gelu_exact(fmaf(c, W1[j], b1[j]));
  float h2[8];
#pragma unroll
  for (int k = 0; k < 8; k++) {
    float a = b2[k];
#pragma unroll
    for (int j = 0; j < 16; j++) a = fmaf(h1[j], W2[j * 8 + k], a);
    h2[k] = gelu_exact(a);
  }
  z0 = b3[0]; z1 = b3[1];
#pragma unroll
  for (int k = 0; k < 8; k++) {
    z0 = fmaf(h2[k], W3[2 * k + 0], z0);
    z1 = fmaf(h2[k], W3[2 * k + 1], z1);
  }
}

// ---------------------------------------------------------------------------
// Kernel 0: build Hermite table of f(c) = z0 - z1 and f'(c).
// ---------------------------------------------------------------------------
__global__ void __launch_bounds__(256) build_tab_kernel(
    const float* __restrict__ W1, const float* __restrict__ b1,
    const float* __restrict__ W2, const float* __restrict__ b2,
    const float* __restrict__ W3, const float* __restrict__ b3)
{
  int i = blockIdx.x * blockDim.x + threadIdx.x;
  if (i > TAB_N) return;
  float c = (float)(i - TAB_N / 2) * TAB_H;   // -128 .. 128

  float h1[16], dh1[16];
#pragma unroll
  for (int j = 0; j < 16; j++) {
    float a = fmaf(c, W1[j], b1[j]);
    float e = erff(a * 0.70710678118654752440f);
    float phi = 0.3989422804014327f * expf(-0.5f * a * a);
    h1[j]  = 0.5f * a * (1.0f + e);
    dh1[j] = (0.5f * (1.0f + e) + a * phi) * W1[j];
  }
  float h2[8], dh2[8];
#pragma unroll
  for (int k = 0; k < 8; k++) {
    float a = b2[k], da = 0.f;
#pragma unroll
    for (int j = 0; j < 16; j++) {
      a  = fmaf(h1[j],  W2[j * 8 + k], a);
      da = fmaf(dh1[j], W2[j * 8 + k], da);
    }
    float e = erff(a * 0.70710678118654752440f);
    float phi = 0.3989422804014327f * expf(-0.5f * a * a);
    h2[k]  = 0.5f * a * (1.0f + e);
    dh2[k] = (0.5f * (1.0f + e) + a * phi) * da;
  }
  float z0 = b3[0], z1 = b3[1], d0 = 0.f, d1 = 0.f;
#pragma unroll
  for (int k = 0; k < 8; k++) {
    z0 = fmaf(h2[k],  W3[2 * k + 0], z0);
    z1 = fmaf(h2[k],  W3[2 * k + 1], z1);
    d0 = fmaf(dh2[k], W3[2 * k + 0], d0);
    d1 = fmaf(dh2[k], W3[2 * k + 1], d1);
  }
  g_tab[i] = make_float2(z0 - z1, d0 - d1);
}

// ---------------------------------------------------------------------------
// Fast adjacency bit: spline margin + gumbel saturation skip.
//   |g0-g1| <= 19.08 (u in [1e-10, 1-2^-23] => g in [-3.137, 15.943])
// ---------------------------------------------------------------------------
__device__ __forceinline__ float hard_bit_fast(float c, uint32_t q,
    const float* __restrict__ sW1, const float* __restrict__ sb1,
    const float* __restrict__ sW2, const float* __restrict__ sb2,
    const float* __restrict__ sW3, const float* __restrict__ sb3)
{
  float d;
  float u = fmaf(c, TAB_SCALE, (float)(TAB_N / 2));
  float fl = floorf(u);
  int i = (int)fl;
  if (i >= 0 && i < TAB_N) {
    float t = u - fl;
    float2 p0 = g_tab[i];
    float2 p1 = g_tab[i + 1];
    float m0 = p0.y * TAB_H, m1 = p1.y * TAB_H;
    float t2 = t * t, t3 = t2 * t;
    d = p0.x * (2.f * t3 - 3.f * t2 + 1.f) + m0 * (t3 - 2.f * t2 + t)
      + p1.x * (3.f * t2 - 2.f * t3)       + m1 * (t3 - t2);
  } else {
    float z0, z1;                              // |c| >= 128: essentially never
    mlp_z(c, sW1, sb1, sW2, sb2, sW3, sb3, z0, z1);
    d = z0 - z1;
  }
  if (d >  19.5f) return 1.0f;                 // gumbel can never flip it
  if (d < -19.5f) return 0.0f;
  float g0 = bits_to_gumbel(jax_bits(2u * q));
  float g1 = bits_to_gumbel(jax_bits(2u * q + 1u));
  return (d + g0 >= g1) ? 1.0f : 0.0f;
}

// ---------------------------------------------------------------------------
// Kernel 1: adjacency bits.  corr = fm[b] @ fm[b]^T (64x64 tile), epilogue via
// spline table + saturation-skipped gumbel.  Writes g_adj in {0,1}.
// ---------------------------------------------------------------------------
__global__ void __launch_bounds__(256) adj_kernel(
    const float* __restrict__ fm,
    const float* __restrict__ W1, const float* __restrict__ b1,
    const float* __restrict__ W2, const float* __restrict__ b2,
    const float* __restrict__ W3, const float* __restrict__ b3)
{
  __shared__ float As[16][64];
  __shared__ float Bs[16][64];
  __shared__ float sW1[16], sb1[16], sW2[128], sb2[8], sW3[16], sb3[2];

  const int tid = threadIdx.x;
  const int b  = blockIdx.z;
  const int s0 = blockIdx.y * 64;
  const int t0 = blockIdx.x * 64;

  if (tid < 16)        sW1[tid]       = W1[tid];
  else if (tid < 32)   sb1[tid - 16]  = b1[tid - 16];
  else if (tid < 160)  sW2[tid - 32]  = W2[tid - 32];
  else if (tid < 168)  sb2[tid - 160] = b2[tid - 160];
  else if (tid < 184)  sW3[tid - 168] = W3[tid - 168];
  else if (tid < 186)  sb3[tid - 184] = b3[tid - 184];

  const float* A = fm + (size_t)b * NS * NL;
  const int lr = tid >> 2;           // 0..63
  const int lc = (tid & 3) << 2;     // 0,4,8,12
  const int ty = tid >> 4;           // 0..15
  const int tx = tid & 15;           // 0..15

  float acc[4][4];
#pragma unroll
  for (int i = 0; i < 4; i++)
#pragma unroll
    for (int j = 0; j < 4; j++) acc[i][j] = 0.f;

  for (int k0 = 0; k0 < NL; k0 += 16) {
    float4 av = *reinterpret_cast<const float4*>(A + (s0 + lr) * NL + k0 + lc);
    float4 bv = *reinterpret_cast<const float4*>(A + (t0 + lr) * NL + k0 + lc);
    __syncthreads();
    As[lc + 0][lr] = av.x; As[lc + 1][lr] = av.y; As[lc + 2][lr] = av.z; As[lc + 3][lr] = av.w;
    Bs[lc + 0][lr] = bv.x; Bs[lc + 1][lr] = bv.y; Bs[lc + 2][lr] = bv.z; Bs[lc + 3][lr] = bv.w;
    __syncthreads();
#pragma unroll
    for (int k = 0; k < 16; k++) {
      float4 a  = *reinterpret_cast<const float4*>(&As[k][ty << 2]);
      float4 bb = *reinterpret_cast<const float4*>(&Bs[k][tx << 2]);
      acc[0][0] = fmaf(a.x, bb.x, acc[0][0]); acc[0][1] = fmaf(a.x, bb.y, acc[0][1]);
      acc[0][2] = fmaf(a.x, bb.z, acc[0][2]); acc[0][3] = fmaf(a.x, bb.w, acc[0][3]);
      acc[1][0] = fmaf(a.y, bb.x, acc[1][0]); acc[1][1] = fmaf(a.y, bb.y, acc[1][1]);
      acc[1][2] = fmaf(a.y, bb.z, acc[1][2]); acc[1][3] = fmaf(a.y, bb.w, acc[1][3]);
      acc[2][0] = fmaf(a.z, bb.x, acc[2][0]); acc[2][1] = fmaf(a.z, bb.y, acc[2][1]);
      acc[2][2] = fmaf(a.z, bb.z, acc[2][2]); acc[2][3] = fmaf(a.z, bb.w, acc[2][3]);
      acc[3][0] = fmaf(a.w, bb.x, acc[3][0]); acc[3][1] = fmaf(a.w, bb.y, acc[3][1]);
      acc[3][2] = fmaf(a.w, bb.z, acc[3][2]); acc[3][3] = fmaf(a.w, bb.w, acc[3][3]);
    }
  }

#pragma unroll
  for (int i = 0; i < 4; i++) {
    int s = s0 + (ty << 2) + i;
#pragma unroll
    for (int j = 0; j < 4; j++) {
      int t = t0 + (tx << 2) + j;
      uint32_t q = ((uint32_t)b << 16) | ((uint32_t)s << 8) | (uint32_t)t;
      float bit;
      if (s == t) bit = 1.0f;
      else bit = hard_bit_fast(acc[i][j], q, sW1, sb1, sW2, sb2, sW3, sb3);
      g_adj[q] = bit;
    }
  }
}

// ---------------------------------------------------------------------------
// Kernel 2: inverse degree per row (exact: {0,1} entries sum exactly)
// ---------------------------------------------------------------------------
__global__ void __launch_bounds__(256) invdeg_kernel() {
  int warp = (blockIdx.x * blockDim.x + threadIdx.x) >> 5;
  int lane = threadIdx.x & 31;
  if (warp >= NB * NS) return;
  const float* row = g_adj + (size_t)warp * NS;
  float s = 0.f;
#pragma unroll
  for (int t = lane; t < NS; t += 32) s += row[t];
#pragma unroll
  for (int o = 16; o; o >>= 1) s += __shfl_xor_sync(0xFFFFFFFFu, s, o);
  if (lane == 0) g_invdeg[warp] = 1.0f / s;
}

// ---------------------------------------------------------------------------
// Kernel 3: Y[bc] = invdeg * (adj[b] @ F[bc])   (128x128x8 double-buffered)
// ---------------------------------------------------------------------------
__global__ void __launch_bounds__(256) prop_kernel(const float* __restrict__ features) {
  __shared__ float As[2][8][128];
  __shared__ float Bs[2][8][128];

  const int tid = threadIdx.x;
  const int bc = blockIdx.z;
  const int b  = bc >> 2;
  const int s0 = blockIdx.y * 128;
  const int d0 = blockIdx.x * 128;

  const float* A  = g_adj + (size_t)b * NS * NS;
  const float* Bm = features + (size_t)bc * NS * NDIN;

  const int ar = tid >> 1;
  const int ac = (tid & 1) << 2;
  const int brow = tid >> 5;
  const int bcol = (tid & 31) << 2;
  const int ty = tid >> 4;
  const int tx = tid & 15;

  float acc[8][8];
#pragma unroll
  for (int i = 0; i < 8; i++)
#pragma unroll
    for (int j = 0; j < 8; j++) acc[i][j] = 0.f;

  float4 av = *reinterpret_cast<const float4*>(A  + (s0 + ar) * NS + ac);
  float4 bv = *reinterpret_cast<const float4*>(Bm + brow * NDIN + d0 + bcol);
  As[0][ac + 0][ar] = av.x; As[0][ac + 1][ar] = av.y;
  As[0][ac + 2][ar] = av.z; As[0][ac + 3][ar] = av.w;
  *reinterpret_cast<float4*>(&Bs[0][brow][bcol]) = bv;
  __syncthreads();

  const int NK = NS / 8;
  for (int kt = 0; kt < NK; kt++) {
    const int cur = kt & 1;
    if (kt + 1 < NK) {
      int k0 = (kt + 1) * 8;
      av = *reinterpret_cast<const float4*>(A  + (s0 + ar) * NS + k0 + ac);
      bv = *reinterpret_cast<const float4*>(Bm + (k0 + brow) * NDIN + d0 + bcol);
    }
#pragma unroll
    for (int k = 0; k < 8; k++) {
      float4 a0 = *reinterpret_cast<const float4*>(&As[cur][k][ty * 8 + 0]);
      float4 a1 = *reinterpret_cast<const float4*>(&As[cur][k][ty * 8 + 4]);
      float4 b0 = *reinterpret_cast<const float4*>(&Bs[cur][k][tx * 8 + 0]);
      float4 b1 = *reinterpret_cast<const float4*>(&Bs[cur][k][tx * 8 + 4]);
      float ar_[8] = {a0.x, a0.y, a0.z, a0.w, a1.x, a1.y, a1.z, a1.w};
      float br_[8] = {b0.x, b0.y, b0.z, b0.w, b1.x, b1.y, b1.z, b1.w};
#pragma unroll
      for (int i = 0; i < 8; i++)
#pragma unroll
        for (int j = 0; j < 8; j++)
          acc[i][j] = fmaf(ar_[i], br_[j], acc[i][j]);
    }
    if (kt + 1 < NK) {
      const int nxt = 1 - cur;
      As[nxt][ac + 0][ar] = av.x; As[nxt][ac + 1][ar] = av.y;
      As[nxt][ac + 2][ar] = av.z; As[nxt][ac + 3][ar] = av.w;
      *reinterpret_cast<float4*>(&Bs[nxt][brow][bcol]) = bv;
      __syncthreads();
    }
  }

#pragma unroll
  for (int i = 0; i < 8; i++) {
    int s = s0 + ty * 8 + i;
    float sc = g_invdeg[b * NS + s];
    float4 v0 = make_float4(sc * acc[i][0], sc * acc[i][1], sc * acc[i][2], sc * acc[i][3]);
    float4 v1 = make_float4(sc * acc[i][4], sc * acc[i][5], sc * acc[i][6], sc * acc[i][7]);
    float* dst = &g_Y[((size_t)bc * NS + s) * NDIN + d0 + tx * 8];
    *reinterpret_cast<float4*>(dst + 0) = v0;
    *reinterpret_cast<float4*>(dst + 4) = v1;
  }
}

// ---------------------------------------------------------------------------
// Kernel 4: out = Y @ Wl + bl    (32768 x 256 x 256)
// ---------------------------------------------------------------------------
__global__ void __launch_bounds__(256) out_kernel(const float* __restrict__ Wl,
                                                  const float* __restrict__ bl,
                                                  float* __restrict__ out) {
  __shared__ float As[2][8][128];
  __shared__ float Bs[2][8][128];

  const int tid = threadIdx.x;
  const int m0 = blockIdx.y * 128;
  const int n0 = blockIdx.x * 128;

  const int ar = tid >> 1;
  const int ac = (tid & 1) << 2;
  const int brow = tid >> 5;
  const int bcol = (tid & 31) << 2;
  const int ty = tid >> 4;
  const int tx = tid & 15;

  float acc[8][8];
#pragma unroll
  for (int i = 0; i < 8; i++)
#pragma unroll
    for (int j = 0; j < 8; j++) acc[i][j] = 0.f;

  float4 av = *reinterpret_cast<const float4*>(&g_Y[(size_t)(m0 + ar) * NDIN + ac]);
  float4 bv = *reinterpret_cast<const float4*>(Wl + brow * NDOUT + n0 + bcol);
  As[0][ac + 0][ar] = av.x; As[0][ac + 1][ar] = av.y;
  As[0][ac + 2][ar] = av.z; As[0][ac + 3][ar] = av.w;
  *reinterpret_cast<float4*>(&Bs[0][brow][bcol]) = bv;
  __syncthreads();

  const int NK = NDIN / 8;
  for (int kt = 0; kt < NK; kt++) {
    const int cur = kt & 1;
    if (kt + 1 < NK) {
      int k0 = (kt + 1) * 8;
      av = *reinterpret_cast<const float4*>(&g_Y[(size_t)(m0 + ar) * NDIN + k0 + ac]);
      bv = *reinterpret_cast<const float4*>(Wl + (k0 + brow) * NDOUT + n0 + bcol);
    }
#pragma unroll
    for (int k = 0; k < 8; k++) {
      float4 a0 = *reinterpret_cast<const float4*>(&As[cur][k][ty * 8 + 0]);
      float4 a1 = *reinterpret_cast<const float4*>(&As[cur][k][ty * 8 + 4]);
      float4 b0 = *reinterpret_cast<const float4*>(&Bs[cur][k][tx * 8 + 0]);
      float4 b1 = *reinterpret_cast<const float4*>(&Bs[cur][k][tx * 8 + 4]);
      float ar_[8] = {a0.x, a0.y, a0.z, a0.w, a1.x, a1.y, a1.z, a1.w};
      float br_[8] = {b0.x, b0.y, b0.z, b0.w, b1.x, b1.y, b1.z, b1.w};
#pragma unroll
      for (int i = 0; i < 8; i++)
#pragma unroll
        for (int j = 0; j < 8; j++)
          acc[i][j] = fmaf(ar_[i], br_[j], acc[i][j]);
    }
    if (kt + 1 < NK) {
      const int nxt = 1 - cur;
      As[nxt][ac + 0][ar] = av.x; As[nxt][ac + 1][ar] = av.y;
      As[nxt][ac + 2][ar] = av.z; As[nxt][ac + 3][ar] = av.w;
      *reinterpret_cast<float4*>(&Bs[nxt][brow][bcol]) = bv;
      __syncthreads();
    }
  }

  float4 bias0 = *reinterpret_cast<const float4*>(bl + n0 + tx * 8 + 0);
  float4 bias1 = *reinterpret_cast<const float4*>(bl + n0 + tx * 8 + 4);
#pragma unroll
  for (int i = 0; i < 8; i++) {
    int m = m0 + ty * 8 + i;
    float4 v0 = make_float4(acc[i][0] + bias0.x, acc[i][1] + bias0.y,
                            acc[i][2] + bias0.z, acc[i][3] + bias0.w);
    float4 v1 = make_float4(acc[i][4] + bias1.x, acc[i][5] + bias1.y,
                            acc[i][6] + bias1.z, acc[i][7] + bias1.w);
    float* dst = &out[(size_t)m * NDOUT + n0 + tx * 8];
    *reinterpret_cast<float4*>(dst + 0) = v0;
    *reinterpret_cast<float4*>(dst + 4) = v1;
  }
}

// ---------------------------------------------------------------------------
extern "C" void kernel_launch(void* const* d_in, const int* in_sizes, int n_in,
                              void* d_out, int out_size) {
  const float *features = 0, *fm = 0, *W1 = 0, *b1 = 0, *W2 = 0, *b2 = 0,
              *W3 = 0, *b3 = 0, *Wl = 0, *bl = 0;
  int n16 = 0;
  for (int i = 0; i < n_in; i++) {
    const float* p = (const float*)d_in[i];
    switch (in_sizes[i]) {
      case 8388608: features = p; break;
      case 2097152: fm = p; break;
      case 128:     W2 = p; break;
      case 8:       b2 = p; break;
      case 2:       b3 = p; break;
      case 65536:   Wl = p; break;
      case 256:     bl = p; break;
      case 16:
        if (n16 == 0) W1 = p; else if (n16 == 1) b1 = p; else W3 = p;
        n16++; break;
      default: break;
    }
  }
  float* out = (float*)d_out;

  build_tab_kernel<<<(TAB_N + 256) / 256, 256>>>(W1, b1, W2, b2, W3, b3);
  adj_kernel<<<dim3(4, 4, 32), 256>>>(fm, W1, b1, W2, b2, W3, b3);
  invdeg_kernel<<<(NB * NS) / 8, 256>>>();
  prop_kernel<<<dim3(2, 2, 128), 256>>>(features);
  out_kernel<<<dim3(2, 256, 1), 256>>>(Wl, bl, out);
}

// round 11
// speedup vs baseline: 2.3326x; 1.6015x over previous
#include <cuda_runtime.h>
#include <stdint.h>

#define NB 32
#define NC 4
#define NS 256
#define NL 256
#define NDIN 256
#define NDOUT 256

#define TAB_N 16384
#define TAB_SCALE 64.0f
#define TAB_H (1.0f / 64.0f)

__device__ float g_adj[NB * NS * NS];
__device__ float g_invdeg[NB * NS];
__device__ float g_Y[(size_t)NB * NC * NS * NDIN];
__device__ float2 g_tab[TAB_N + 1];

// ---------------------------------------------------------------------------
// Threefry-2x32, key=(0,42); partitionable XOR-fold bits (JAX >= 0.4.36)
// ---------------------------------------------------------------------------
__device__ __forceinline__ void threefry(uint32_t x0, uint32_t x1,
                                         uint32_t& o0, uint32_t& o1) {
  const uint32_t ks0 = 0u;
  const uint32_t ks1 = 42u;
  const uint32_t ks2 = 0u ^ 42u ^ 0x1BD11BDAu;
  x0 += ks0; x1 += ks1;
#define TF_R(r) { x0 += x1; x1 = __funnelshift_l(x1, x1, (r)); x1 ^= x0; }
  TF_R(13) TF_R(15) TF_R(26) TF_R(6)
  x0 += ks1; x1 += ks2 + 1u;
  TF_R(17) TF_R(29) TF_R(16) TF_R(24)
  x0 += ks2; x1 += ks0 + 2u;
  TF_R(13) TF_R(15) TF_R(26) TF_R(6)
  x0 += ks0; x1 += ks1 + 3u;
  TF_R(17) TF_R(29) TF_R(16) TF_R(24)
  x0 += ks1; x1 += ks2 + 4u;
  TF_R(13) TF_R(15) TF_R(26) TF_R(6)
  x0 += ks2; x1 += ks0 + 5u;
#undef TF_R
  o0 = x0; o1 = x1;
}

__device__ __forceinline__ uint32_t jax_bits(uint32_t p) {
  uint32_t o0, o1;
  threefry(0u, p, o0, o1);
  return o0 ^ o1;
}

__device__ __forceinline__ float bits_to_gumbel(uint32_t bits) {
  float f = __uint_as_float((bits >> 9) | 0x3F800000u) - 1.0f;
  float u = fmaxf(1e-10f, f + 1e-10f);
  return -logf(-logf(u));
}

__device__ __forceinline__ float gelu_exact(float x) {
  return 0.5f * x * (1.0f + erff(x * 0.70710678118654752440f));
}

// TF32 helpers
__device__ __forceinline__ uint32_t to_tf32(float x) {
  uint32_t r;
  asm("cvt.rna.tf32.f32 %0, %1;" : "=r"(r) : "f"(x));
  return r;
}
__device__ __forceinline__ void mma_tf32(float c[4],
    uint32_t a0, uint32_t a1, uint32_t a2, uint32_t a3,
    uint32_t b0, uint32_t b1) {
  asm volatile(
    "mma.sync.aligned.m16n8k8.row.col.f32.tf32.tf32.f32 "
    "{%0,%1,%2,%3}, {%4,%5,%6,%7}, {%8,%9}, {%0,%1,%2,%3};"
    : "+f"(c[0]), "+f"(c[1]), "+f"(c[2]), "+f"(c[3])
    : "r"(a0), "r"(a1), "r"(a2), "r"(a3), "r"(b0), "r"(b1));
}

// ---------------------------------------------------------------------------
// Exact MLP margin (fallback for |c| >= 128 — essentially never taken)
// ---------------------------------------------------------------------------
__device__ __forceinline__ void mlp_z(float c,
    const float* __restrict__ W1, const float* __restrict__ b1,
    const float* __restrict__ W2, const float* __restrict__ b2,
    const float* __restrict__ W3, const float* __restrict__ b3,
    float& z0, float& z1)
{
  float h1[16];
#pragma unroll
  for (int j = 0; j < 16; j++) h1[j] = gelu_exact(fmaf(c, W1[j], b1[j]));
  float h2[8];
#pragma unroll
  for (int k = 0; k < 8; k++) {
    float a = b2[k];
#pragma unroll
    for (int j = 0; j < 16; j++) a = fmaf(h1[j], W2[j * 8 + k], a);
    h2[k] = gelu_exact(a);
  }
  z0 = b3[0]; z1 = b3[1];
#pragma unroll
  for (int k = 0; k < 8; k++) {
    z0 = fmaf(h2[k], W3[2 * k + 0], z0);
    z1 = fmaf(h2[k], W3[2 * k + 1], z1);
  }
}

// ---------------------------------------------------------------------------
// Kernel 0: Hermite table of f(c)=z0-z1, f'(c)
// ---------------------------------------------------------------------------
__global__ void __launch_bounds__(256) build_tab_kernel(
    const float* __restrict__ W1, const float* __restrict__ b1,
    const float* __restrict__ W2, const float* __restrict__ b2,
    const float* __restrict__ W3, const float* __restrict__ b3)
{
  int i = blockIdx.x * blockDim.x + threadIdx.x;
  if (i > TAB_N) return;
  float c = (float)(i - TAB_N / 2) * TAB_H;

  float h1[16], dh1[16];
#pragma unroll
  for (int j = 0; j < 16; j++) {
    float a = fmaf(c, W1[j], b1[j]);
    float e = erff(a * 0.70710678118654752440f);
    float phi = 0.3989422804014327f * expf(-0.5f * a * a);
    h1[j]  = 0.5f * a * (1.0f + e);
    dh1[j] = (0.5f * (1.0f + e) + a * phi) * W1[j];
  }
  float h2[8], dh2[8];
#pragma unroll
  for (int k = 0; k < 8; k++) {
    float a = b2[k], da = 0.f;
#pragma unroll
    for (int j = 0; j < 16; j++) {
      a  = fmaf(h1[j],  W2[j * 8 + k], a);
      da = fmaf(dh1[j], W2[j * 8 + k], da);
    }
    float e = erff(a * 0.70710678118654752440f);
    float phi = 0.3989422804014327f * expf(-0.5f * a * a);
    h2[k]  = 0.5f * a * (1.0f + e);
    dh2[k] = (0.5f * (1.0f + e) + a * phi) * da;
  }
  float z0 = b3[0], z1 = b3[1], d0 = 0.f, d1 = 0.f;
#pragma unroll
  for (int k = 0; k < 8; k++) {
    z0 = fmaf(h2[k],  W3[2 * k + 0], z0);
    z1 = fmaf(h2[k],  W3[2 * k + 1], z1);
    d0 = fmaf(dh2[k], W3[2 * k + 0], d0);
    d1 = fmaf(dh2[k], W3[2 * k + 1], d1);
  }
  g_tab[i] = make_float2(z0 - z1, d0 - d1);
}

// ---------------------------------------------------------------------------
// Fast adjacency bit: spline margin + gumbel saturation skip
// ---------------------------------------------------------------------------
__device__ __forceinline__ float hard_bit_fast(float c, uint32_t q,
    const float* __restrict__ sW1, const float* __restrict__ sb1,
    const float* __restrict__ sW2, const float* __restrict__ sb2,
    const float* __restrict__ sW3, const float* __restrict__ sb3)
{
  float d;
  float u = fmaf(c, TAB_SCALE, (float)(TAB_N / 2));
  float fl = floorf(u);
  int i = (int)fl;
  if (i >= 0 && i < TAB_N) {
    float t = u - fl;
    float2 p0 = g_tab[i];
    float2 p1 = g_tab[i + 1];
    float m0 = p0.y * TAB_H, m1 = p1.y * TAB_H;
    float t2 = t * t, t3 = t2 * t;
    d = p0.x * (2.f * t3 - 3.f * t2 + 1.f) + m0 * (t3 - 2.f * t2 + t)
      + p1.x * (3.f * t2 - 2.f * t3)       + m1 * (t3 - t2);
  } else {
    float z0, z1;
    mlp_z(c, sW1, sb1, sW2, sb2, sW3, sb3, z0, z1);
    d = z0 - z1;
  }
  if (d >  19.5f) return 1.0f;
  if (d < -19.5f) return 0.0f;
  float g0 = bits_to_gumbel(jax_bits(2u * q));
  float g1 = bits_to_gumbel(jax_bits(2u * q + 1u));
  return (d + g0 >= g1) ? 1.0f : 0.0f;
}

// ---------------------------------------------------------------------------
// Kernel 1: adjacency bits (64x64 fp32 GEMM tile + fast epilogue)
// ---------------------------------------------------------------------------
__global__ void __launch_bounds__(256) adj_kernel(
    const float* __restrict__ fm,
    const float* __restrict__ W1, const float* __restrict__ b1,
    const float* __restrict__ W2, const float* __restrict__ b2,
    const float* __restrict__ W3, const float* __restrict__ b3)
{
  __shared__ float As[16][64];
  __shared__ float Bs[16][64];
  __shared__ float sW1[16], sb1[16], sW2[128], sb2[8], sW3[16], sb3[2];

  const int tid = threadIdx.x;
  const int b  = blockIdx.z;
  const int s0 = blockIdx.y * 64;
  const int t0 = blockIdx.x * 64;

  if (tid < 16)        sW1[tid]       = W1[tid];
  else if (tid < 32)   sb1[tid - 16]  = b1[tid - 16];
  else if (tid < 160)  sW2[tid - 32]  = W2[tid - 32];
  else if (tid < 168)  sb2[tid - 160] = b2[tid - 160];
  else if (tid < 184)  sW3[tid - 168] = W3[tid - 168];
  else if (tid < 186)  sb3[tid - 184] = b3[tid - 184];

  const float* A = fm + (size_t)b * NS * NL;
  const int lr = tid >> 2;
  const int lc = (tid & 3) << 2;
  const int ty = tid >> 4;
  const int tx = tid & 15;

  float acc[4][4];
#pragma unroll
  for (int i = 0; i < 4; i++)
#pragma unroll
    for (int j = 0; j < 4; j++) acc[i][j] = 0.f;

  for (int k0 = 0; k0 < NL; k0 += 16) {
    float4 av = *reinterpret_cast<const float4*>(A + (s0 + lr) * NL + k0 + lc);
    float4 bv = *reinterpret_cast<const float4*>(A + (t0 + lr) * NL + k0 + lc);
    __syncthreads();
    As[lc + 0][lr] = av.x; As[lc + 1][lr] = av.y; As[lc + 2][lr] = av.z; As[lc + 3][lr] = av.w;
    Bs[lc + 0][lr] = bv.x; Bs[lc + 1][lr] = bv.y; Bs[lc + 2][lr] = bv.z; Bs[lc + 3][lr] = bv.w;
    __syncthreads();
#pragma unroll
    for (int k = 0; k < 16; k++) {
      float4 a  = *reinterpret_cast<const float4*>(&As[k][ty << 2]);
      float4 bb = *reinterpret_cast<const float4*>(&Bs[k][tx << 2]);
      acc[0][0] = fmaf(a.x, bb.x, acc[0][0]); acc[0][1] = fmaf(a.x, bb.y, acc[0][1]);
      acc[0][2] = fmaf(a.x, bb.z, acc[0][2]); acc[0][3] = fmaf(a.x, bb.w, acc[0][3]);
      acc[1][0] = fmaf(a.y, bb.x, acc[1][0]); acc[1][1] = fmaf(a.y, bb.y, acc[1][1]);
      acc[1][2] = fmaf(a.y, bb.z, acc[1][2]); acc[1][3] = fmaf(a.y, bb.w, acc[1][3]);
      acc[2][0] = fmaf(a.z, bb.x, acc[2][0]); acc[2][1] = fmaf(a.z, bb.y, acc[2][1]);
      acc[2][2] = fmaf(a.z, bb.z, acc[2][2]); acc[2][3] = fmaf(a.z, bb.w, acc[2][3]);
      acc[3][0] = fmaf(a.w, bb.x, acc[3][0]); acc[3][1] = fmaf(a.w, bb.y, acc[3][1]);
      acc[3][2] = fmaf(a.w, bb.z, acc[3][2]); acc[3][3] = fmaf(a.w, bb.w, acc[3][3]);
    }
  }

#pragma unroll
  for (int i = 0; i < 4; i++) {
    int s = s0 + (ty << 2) + i;
#pragma unroll
    for (int j = 0; j < 4; j++) {
      int t = t0 + (tx << 2) + j;
      uint32_t q = ((uint32_t)b << 16) | ((uint32_t)s << 8) | (uint32_t)t;
      float bit;
      if (s == t) bit = 1.0f;
      else bit = hard_bit_fast(acc[i][j], q, sW1, sb1, sW2, sb2, sW3, sb3);
      g_adj[q] = bit;
    }
  }
}

// ---------------------------------------------------------------------------
// Kernel 2: inverse degree per row
// ---------------------------------------------------------------------------
__global__ void __launch_bounds__(256) invdeg_kernel() {
  int warp = (blockIdx.x * blockDim.x + threadIdx.x) >> 5;
  int lane = threadIdx.x & 31;
  if (warp >= NB * NS) return;
  const float* row = g_adj + (size_t)warp * NS;
  float s = 0.f;
#pragma unroll
  for (int t = lane; t < NS; t += 32) s += row[t];
#pragma unroll
  for (int o = 16; o; o >>= 1) s += __shfl_xor_sync(0xFFFFFFFFu, s, o);
  if (lane == 0) g_invdeg[warp] = 1.0f / s;
}

// ---------------------------------------------------------------------------
// TF32 tensor-core GEMM core: 128x128 block, 8 warps x (64x32 warp tile),
// k-tile 8 double-buffered.  A smem [128][12] (pad), B smem [8][132] (pad).
// ---------------------------------------------------------------------------
#define APAD 12
#define BPAD 132

// Kernel 3: Y[bc] = invdeg * (adj[b] @ F[bc])   — A (adj) is exact in tf32
__global__ void __launch_bounds__(256) prop_kernel(const float* __restrict__ features) {
  __shared__ uint32_t As[2][128][APAD];
  __shared__ uint32_t Bs[2][8][BPAD];

  const int tid = threadIdx.x;
  const int bc = blockIdx.z;
  const int b  = bc >> 2;
  const int s0 = blockIdx.y * 128;
  const int d0 = blockIdx.x * 128;

  const float* A  = g_adj + (size_t)b * NS * NS;
  const float* Bm = features + (size_t)bc * NS * NDIN;

  const int ar = tid >> 1, ac = (tid & 1) << 2;
  const int brow = tid >> 5, bcol = (tid & 31) << 2;

  const int wid = tid >> 5, lane = tid & 31;
  const int wm = (wid >> 2) * 64, wn = (wid & 3) * 32;
  const int gid = lane >> 2, t4 = lane & 3;

  float c[4][4][4];
#pragma unroll
  for (int i = 0; i < 4; i++)
#pragma unroll
    for (int j = 0; j < 4; j++)
#pragma unroll
      for (int r = 0; r < 4; r++) c[i][j][r] = 0.f;

  // preload tile 0
  {
    float4 av = *reinterpret_cast<const float4*>(A  + (s0 + ar) * NS + ac);
    float4 bv = *reinterpret_cast<const float4*>(Bm + brow * NDIN + d0 + bcol);
    As[0][ar][ac + 0] = to_tf32(av.x); As[0][ar][ac + 1] = to_tf32(av.y);
    As[0][ar][ac + 2] = to_tf32(av.z); As[0][ar][ac + 3] = to_tf32(av.w);
    Bs[0][brow][bcol + 0] = to_tf32(bv.x); Bs[0][brow][bcol + 1] = to_tf32(bv.y);
    Bs[0][brow][bcol + 2] = to_tf32(bv.z); Bs[0][brow][bcol + 3] = to_tf32(bv.w);
  }
  __syncthreads();

  const int NK = NS / 8;
  for (int kt = 0; kt < NK; kt++) {
    const int cur = kt & 1;
    float4 av, bv;
    if (kt + 1 < NK) {
      int k0 = (kt + 1) * 8;
      av = *reinterpret_cast<const float4*>(A  + (s0 + ar) * NS + k0 + ac);
      bv = *reinterpret_cast<const float4*>(Bm + (k0 + brow) * NDIN + d0 + bcol);
    }
    uint32_t afr[4][4], bfr[4][2];
#pragma unroll
    for (int i = 0; i < 4; i++) {
      int row = wm + i * 16 + gid;
      afr[i][0] = As[cur][row][t4];
      afr[i][1] = As[cur][row + 8][t4];
      afr[i][2] = As[cur][row][t4 + 4];
      afr[i][3] = As[cur][row + 8][t4 + 4];
    }
#pragma unroll
    for (int j = 0; j < 4; j++) {
      int col = wn + j * 8 + gid;
      bfr[j][0] = Bs[cur][t4][col];
      bfr[j][1] = Bs[cur][t4 + 4][col];
    }
#pragma unroll
    for (int i = 0; i < 4; i++)
#pragma unroll
      for (int j = 0; j < 4; j++)
        mma_tf32(c[i][j], afr[i][0], afr[i][1], afr[i][2], afr[i][3],
                 bfr[j][0], bfr[j][1]);
    if (kt + 1 < NK) {
      const int nxt = 1 - cur;
      As[nxt][ar][ac + 0] = to_tf32(av.x); As[nxt][ar][ac + 1] = to_tf32(av.y);
      As[nxt][ar][ac + 2] = to_tf32(av.z); As[nxt][ar][ac + 3] = to_tf32(av.w);
      Bs[nxt][brow][bcol + 0] = to_tf32(bv.x); Bs[nxt][brow][bcol + 1] = to_tf32(bv.y);
      Bs[nxt][brow][bcol + 2] = to_tf32(bv.z); Bs[nxt][brow][bcol + 3] = to_tf32(bv.w);
      __syncthreads();
    }
  }

#pragma unroll
  for (int i = 0; i < 4; i++) {
    int r0 = s0 + wm + i * 16 + gid;
    int r1 = r0 + 8;
    float sc0 = g_invdeg[b * NS + r0];
    float sc1 = g_invdeg[b * NS + r1];
#pragma unroll
    for (int j = 0; j < 4; j++) {
      int col = d0 + wn + j * 8 + 2 * t4;
      float* p0 = &g_Y[((size_t)bc * NS + r0) * NDIN + col];
      float* p1 = &g_Y[((size_t)bc * NS + r1) * NDIN + col];
      *reinterpret_cast<float2*>(p0) = make_float2(sc0 * c[i][j][0], sc0 * c[i][j][1]);
      *reinterpret_cast<float2*>(p1) = make_float2(sc1 * c[i][j][2], sc1 * c[i][j][3]);
    }
  }
}

// Kernel 4: out = Y @ Wl + bl   (32768 x 256 x 256, tf32 MMA)
__global__ void __launch_bounds__(256) out_kernel(const float* __restrict__ Wl,
                                                  const float* __restrict__ bl,
                                                  float* __restrict__ out) {
  __shared__ uint32_t As[2][128][APAD];
  __shared__ uint32_t Bs[2][8][BPAD];

  const int tid = threadIdx.x;
  const int m0 = blockIdx.y * 128;
  const int n0 = blockIdx.x * 128;

  const int ar = tid >> 1, ac = (tid & 1) << 2;
  const int brow = tid >> 5, bcol = (tid & 31) << 2;

  const int wid = tid >> 5, lane = tid & 31;
  const int wm = (wid >> 2) * 64, wn = (wid & 3) * 32;
  const int gid = lane >> 2, t4 = lane & 3;

  float c[4][4][4];
#pragma unroll
  for (int i = 0; i < 4; i++)
#pragma unroll
    for (int j = 0; j < 4; j++)
#pragma unroll
      for (int r = 0; r < 4; r++) c[i][j][r] = 0.f;

  {
    float4 av = *reinterpret_cast<const float4*>(&g_Y[(size_t)(m0 + ar) * NDIN + ac]);
    float4 bv = *reinterpret_cast<const float4*>(Wl + brow * NDOUT + n0 + bcol);
    As[0][ar][ac + 0] = to_tf32(av.x); As[0][ar][ac + 1] = to_tf32(av.y);
    As[0][ar][ac + 2] = to_tf32(av.z); As[0][ar][ac + 3] = to_tf32(av.w);
    Bs[0][brow][bcol + 0] = to_tf32(bv.x); Bs[0][brow][bcol + 1] = to_tf32(bv.y);
    Bs[0][brow][bcol + 2] = to_tf32(bv.z); Bs[0][brow][bcol + 3] = to_tf32(bv.w);
  }
  __syncthreads();

  const int NK = NDIN / 8;
  for (int kt = 0; kt < NK; kt++) {
    const int cur = kt & 1;
    float4 av, bv;
    if (kt + 1 < NK) {
      int k0 = (kt + 1) * 8;
      av = *reinterpret_cast<const float4*>(&g_Y[(size_t)(m0 + ar) * NDIN + k0 + ac]);
      bv = *reinterpret_cast<const float4*>(Wl + (k0 + brow) * NDOUT + n0 + bcol);
    }
    uint32_t afr[4][4], bfr[4][2];
#pragma unroll
    for (int i = 0; i < 4; i++) {
      int row = wm + i * 16 + gid;
      afr[i][0] = As[cur][row][t4];
      afr[i][1] = As[cur][row + 8][t4];
      afr[i][2] = As[cur][row][t4 + 4];
      afr[i][3] = As[cur][row + 8][t4 + 4];
    }
#pragma unroll
    for (int j = 0; j < 4; j++) {
      int col = wn + j * 8 + gid;
      bfr[j][0] = Bs[cur][t4][col];
      bfr[j][1] = Bs[cur][t4 + 4][col];
    }
#pragma unroll
    for (int i = 0; i < 4; i++)
#pragma unroll
      for (int j = 0; j < 4; j++)
        mma_tf32(c[i][j], afr[i][0], afr[i][1], afr[i][2], afr[i][3],
                 bfr[j][0], bfr[j][1]);
    if (kt + 1 < NK) {
      const int nxt = 1 - cur;
      As[nxt][ar][ac + 0] = to_tf32(av.x); As[nxt][ar][ac + 1] = to_tf32(av.y);
      As[nxt][ar][ac + 2] = to_tf32(av.z); As[nxt][ar][ac + 3] = to_tf32(av.w);
      Bs[nxt][brow][bcol + 0] = to_tf32(bv.x); Bs[nxt][brow][bcol + 1] = to_tf32(bv.y);
      Bs[nxt][brow][bcol + 2] = to_tf32(bv.z); Bs[nxt][brow][bcol + 3] = to_tf32(bv.w);
      __syncthreads();
    }
  }

#pragma unroll
  for (int i = 0; i < 4; i++) {
    int r0 = m0 + wm + i * 16 + gid;
    int r1 = r0 + 8;
#pragma unroll
    for (int j = 0; j < 4; j++) {
      int col = n0 + wn + j * 8 + 2 * t4;
      float2 bias = *reinterpret_cast<const float2*>(bl + col);
      float* p0 = &out[(size_t)r0 * NDOUT + col];
      float* p1 = &out[(size_t)r1 * NDOUT + col];
      *reinterpret_cast<float2*>(p0) = make_float2(c[i][j][0] + bias.x, c[i][j][1] + bias.y);
      *reinterpret_cast<float2*>(p1) = make_float2(c[i][j][2] + bias.x, c[i][j][3] + bias.y);
    }
  }
}

// ---------------------------------------------------------------------------
extern "C" void kernel_launch(void* const* d_in, const int* in_sizes, int n_in,
                              void* d_out, int out_size) {
  const float *features = 0, *fm = 0, *W1 = 0, *b1 = 0, *W2 = 0, *b2 = 0,
              *W3 = 0, *b3 = 0, *Wl = 0, *bl = 0;
  int n16 = 0;
  for (int i = 0; i < n_in; i++) {
    const float* p = (const float*)d_in[i];
    switch (in_sizes[i]) {
      case 8388608: features = p; break;
      case 2097152: fm = p; break;
      case 128:     W2 = p; break;
      case 8:       b2 = p; break;
      case 2:       b3 = p; break;
      case 65536:   Wl = p; break;
      case 256:     bl = p; break;
      case 16:
        if (n16 == 0) W1 = p; else if (n16 == 1) b1 = p; else W3 = p;
        n16++; break;
      default: break;
    }
  }
  float* out = (float*)d_out;

  build_tab_kernel<<<(TAB_N + 256) / 256, 256>>>(W1, b1, W2, b2, W3, b3);
  adj_kernel<<<dim3(4, 4, 32), 256>>>(fm, W1, b1, W2, b2, W3, b3);
  invdeg_kernel<<<(NB * NS) / 8, 256>>>();
  prop_kernel<<<dim3(2, 2, 128), 256>>>(features);
  out_kernel<<<dim3(2, 256, 1), 256>>>(Wl, bl, out);
}